// round 1
// baseline (speedup 1.0000x reference)
#include <cuda_runtime.h>
#include <math.h>

// ---------------- problem constants ----------------
#define DIMC   256          // model dim
#define SPAT   4096         // 64*64
#define NHEAD  8
#define HDIM   32
#define HIDM   53           // int(32*1.66)
#define MAXB   16

// ---------------- device scratch (no cudaMalloc allowed) ----------------
__device__ float g_mean[MAXB * DIMC];          // per (b,c) spatial mean
__device__ float g_bb[MAXB * 512];             // adjusted bias for [fc1;fcv]
__device__ float g_wcat[512 * DIMC];           // [w_fc1; w_fcv]
__device__ float g_xv[(size_t)MAXB * 512 * SPAT];   // rows 0..255 = x1, 256..511 = value
__device__ float g_x2[(size_t)MAXB * DIMC * SPAT];  // clustering output (unfolded)

// ---------------- packed f32x2 FMA ----------------
__device__ __forceinline__ void ffma2(unsigned long long &d, unsigned long long a, unsigned long long b) {
    asm("fma.rn.f32x2 %0, %1, %2, %0;" : "+l"(d) : "l"(a), "l"(b));
}

// ---------------- kernel 1: spatial mean ----------------
__global__ void mean_kernel(const float* __restrict__ x, float* __restrict__ meanOut) {
    int bc = blockIdx.x;                      // B*256 blocks
    const float* p = x + (size_t)bc * SPAT;
    float s = 0.f;
    for (int i = threadIdx.x; i < SPAT; i += 256) s += p[i];
    __shared__ float red[256];
    red[threadIdx.x] = s;
    __syncthreads();
    for (int off = 128; off > 0; off >>= 1) {
        if (threadIdx.x < off) red[threadIdx.x] += red[threadIdx.x + off];
        __syncthreads();
    }
    if (threadIdx.x == 0) meanOut[bc] = red[0] * (1.f / (float)SPAT);
}

// ---------------- kernel 2a: concat weights ----------------
__global__ void wcat_kernel(const float* __restrict__ w1, const float* __restrict__ wv) {
    int i = blockIdx.x * blockDim.x + threadIdx.x;
    if (i < 65536) g_wcat[i] = w1[i];
    else if (i < 131072) g_wcat[i] = wv[i - 65536];
}

// ---------------- kernel 2b: adjusted bias bb[b, r] ----------------
__global__ void bias_kernel(const float* __restrict__ w1, const float* __restrict__ b1,
                            const float* __restrict__ wv, const float* __restrict__ bv,
                            const float* __restrict__ scaler, int B) {
    int id = blockIdx.x * blockDim.x + threadIdx.x;
    if (id >= B * 512) return;
    int b = id >> 9, r = id & 511;
    const float* w = (r < 256) ? (w1 + (size_t)r * DIMC) : (wv + (size_t)(r - 256) * DIMC);
    float base = (r < 256) ? b1[r] : bv[r - 256];
    const float* mn = g_mean + b * DIMC;
    float s = 0.f;
#pragma unroll 8
    for (int c = 0; c < DIMC; c++) s += w[c] * scaler[c] * mn[c];
    g_bb[id] = base + s;
}

// ---------------- kernel 3/5: SGEMM with f32x2 ----------------
// C[b, m, n] = sum_k W[m,k] * X[b,k,n] + bias
// BM=128, BN=128, BK=8, 256 threads, 8x8 per thread.
// Thread's 8 columns: {tx+16j} and {tx+64+16j}, j=0..3, packed as f32x2 pairs.
#define BM 128
#define BN 128
#define BKK 8

__global__ __launch_bounds__(256, 2)
void sgemm_kernel(const float* __restrict__ W,     // [M, K] row-major
                  const float* __restrict__ X,     // [B, K, S]
                  const float* __restrict__ bias,  // [M] or [B, M]
                  float* __restrict__ O,           // [B, M, S]
                  int M, int K, int S, int biasPerBatch) {
    const int b  = blockIdx.z;
    const int n0 = blockIdx.x * BN;
    const int m0 = blockIdx.y * BM;
    const int tid = threadIdx.x;
    const int tx = tid & 15;
    const int ty = tid >> 4;

    __shared__ __align__(16) float2 As[2][BKK][BM];      // (v,v) duplicated pairs
    __shared__ __align__(16) float2 Bs[2][BKK][BN / 2];  // (col j, col j+64)

    const float* Xb = X + (size_t)b * K * S;

    const int a_row = tid >> 1;
    const int a_kp  = (tid & 1) * 4;
    const int b_kr  = tid >> 5;
    const int b_c4  = (tid & 31) * 4;

    unsigned long long acc[8][4];
#pragma unroll
    for (int i = 0; i < 8; i++)
#pragma unroll
        for (int j = 0; j < 4; j++) acc[i][j] = 0ull;

    // ---- tile loaders ----
    auto loadA = [&](int buf, int k0) {
        float4 v = *reinterpret_cast<const float4*>(W + (size_t)(m0 + a_row) * K + k0 + a_kp);
        As[buf][a_kp + 0][a_row] = make_float2(v.x, v.x);
        As[buf][a_kp + 1][a_row] = make_float2(v.y, v.y);
        As[buf][a_kp + 2][a_row] = make_float2(v.z, v.z);
        As[buf][a_kp + 3][a_row] = make_float2(v.w, v.w);
    };
    auto loadB = [&](int buf, int k0) {
        float4 v = *reinterpret_cast<const float4*>(Xb + (size_t)(k0 + b_kr) * S + n0 + b_c4);
        float vv[4] = {v.x, v.y, v.z, v.w};
#pragma unroll
        for (int i = 0; i < 4; i++) {
            int cc = b_c4 + i;
            if (cc < 64) Bs[buf][b_kr][cc].x = vv[i];
            else         Bs[buf][b_kr][cc - 64].y = vv[i];
        }
    };

    loadA(0, 0);
    loadB(0, 0);
    __syncthreads();

    int buf = 0;
    for (int kt = 0; kt < K; kt += BKK) {
        if (kt + BKK < K) { loadA(buf ^ 1, kt + BKK); loadB(buf ^ 1, kt + BKK); }
#pragma unroll
        for (int k = 0; k < BKK; k++) {
            ulonglong2 a01 = *reinterpret_cast<const ulonglong2*>(&As[buf][k][ty * 8 + 0]);
            ulonglong2 a23 = *reinterpret_cast<const ulonglong2*>(&As[buf][k][ty * 8 + 2]);
            ulonglong2 a45 = *reinterpret_cast<const ulonglong2*>(&As[buf][k][ty * 8 + 4]);
            ulonglong2 a67 = *reinterpret_cast<const ulonglong2*>(&As[buf][k][ty * 8 + 6]);
            unsigned long long aa[8] = {a01.x, a01.y, a23.x, a23.y, a45.x, a45.y, a67.x, a67.y};
            unsigned long long bb4[4];
#pragma unroll
            for (int j = 0; j < 4; j++)
                bb4[j] = *reinterpret_cast<const unsigned long long*>(&Bs[buf][k][tx + 16 * j]);
#pragma unroll
            for (int i = 0; i < 8; i++)
#pragma unroll
                for (int j = 0; j < 4; j++)
                    ffma2(acc[i][j], aa[i], bb4[j]);
        }
        __syncthreads();
        buf ^= 1;
    }

    // ---- epilogue ----
#pragma unroll
    for (int i = 0; i < 8; i++) {
        int row = m0 + ty * 8 + i;
        float bvv = bias[(biasPerBatch ? b * M : 0) + row];
        float* orow = O + ((size_t)b * M + row) * S + n0;
#pragma unroll
        for (int j = 0; j < 4; j++) {
            float lo = __uint_as_float((unsigned)(acc[i][j] & 0xffffffffull));
            float hi = __uint_as_float((unsigned)(acc[i][j] >> 32));
            orow[tx + 16 * j]      = lo + bvv;
            orow[64 + tx + 16 * j] = hi + bvv;
        }
    }
}

// ---------------- kernel 4: clustering (one block per fold window) ----------------
// Window: 32 channels x 32x32 tokens. M=4 clusters, N=1024 tokens.
__global__ __launch_bounds__(256)
void cluster_kernel(const float* __restrict__ w1, const float* __restrict__ bb1,
                    const float* __restrict__ w2, const float* __restrict__ bb2,
                    const float* __restrict__ alphaP, const float* __restrict__ betaP) {
    const int tid = threadIdx.x;
    const int bbk = blockIdx.x;                 // = bh*4 + fi*2 + fj
    const int bh = bbk >> 2;
    const int fi = (bbk >> 1) & 1;
    const int fj = bbk & 1;
    const int batch = bh >> 3;
    const int head = bh & 7;

    const size_t foldoff = (size_t)fi * 32 * 64 + (size_t)fj * 32;
    const float* xbase = g_xv + ((size_t)batch * 512 + head * HDIM) * SPAT + foldoff;
    const float* vbase = xbase + (size_t)256 * SPAT;
    float* obase = g_x2 + ((size_t)batch * DIMC + head * HDIM) * SPAT + foldoff;

    __shared__ float a8[2048];        // [c][pos]  pos=pi*8+pj; reused as MLP output o8
    __shared__ float hbuf[HIDM * 64]; // [j][p]
    __shared__ float w1s[HIDM * HDIM], b1s[HIDM], w2s[HDIM * HIDM], b2s[HDIM];
    __shared__ float ctrs[128], vcs[128], cns[128], outm[128], accs[128], cavg[128];
    __shared__ float cnorm[4], cnt[4];
    __shared__ float simval[1024];
    __shared__ unsigned char mstar[1024];

    // load MLP weights
    for (int i = tid; i < HIDM * HDIM; i += 256) { w1s[i] = w1[i]; w2s[i] = w2[i]; }
    if (tid < HIDM) b1s[tid] = bb1[tid];
    if (tid < HDIM) b2s[tid] = bb2[tid];

    // ---- centers pipeline: pass 0 = value, pass 1 = x ----
    for (int pass = 0; pass < 2; pass++) {
        const float* src = (pass == 0) ? vbase : xbase;
        float* dst = (pass == 0) ? vcs : ctrs;
        __syncthreads();
        // avg-pool 32x32 -> 8x8 per channel
#pragma unroll
        for (int rep = 0; rep < 8; rep++) {
            int e = rep * 256 + tid;
            int c = e >> 6, pos = e & 63, pi = pos >> 3, pj = pos & 7;
            const float* pc = src + (size_t)c * SPAT;
            float s = 0.f;
#pragma unroll
            for (int u = 0; u < 4; u++)
#pragma unroll
                for (int v2 = 0; v2 < 4; v2++)
                    s += pc[(pi * 4 + u) * 64 + pj * 4 + v2];
            a8[c * 64 + pos] = s * (1.f / 16.f);
        }
        __syncthreads();
        // centers avg part (avg of a8 over 4x4 groups)  — reads a8 only
        if (tid < 128) {
            int m = tid >> 5, c = tid & 31, qi = m >> 1, qj = m & 1;
            float s = 0.f;
#pragma unroll
            for (int u = 0; u < 4; u++)
#pragma unroll
                for (int v2 = 0; v2 < 4; v2++)
                    s += a8[c * 64 + (qi * 4 + u) * 8 + qj * 4 + v2];
            cavg[tid] = s * (1.f / 16.f);
        }
        // MLP layer 1 (reads a8, writes hbuf), exact GELU
        for (int eh = tid; eh < HIDM * 64; eh += 256) {
            int j = eh >> 6, p = eh & 63;
            float s = b1s[j];
#pragma unroll
            for (int c = 0; c < HDIM; c++) s += w1s[j * HDIM + c] * a8[c * 64 + p];
            hbuf[eh] = 0.5f * s * (1.f + erff(s * 0.70710678118654752440f));
        }
        __syncthreads();
        // MLP layer 2 -> o8 stored into a8 (a8 dead now)
        for (int eo = tid; eo < 2048; eo += 256) {
            int c = eo >> 6, p = eo & 63;
            float s = b2s[c];
#pragma unroll
            for (int j = 0; j < HIDM; j++) s += w2s[c * HIDM + j] * hbuf[j * 64 + p];
            a8[eo] = s;
        }
        __syncthreads();
        // max-pool 8x8 -> 2x2 and add
        if (tid < 128) {
            int m = tid >> 5, c = tid & 31, qi = m >> 1, qj = m & 1;
            float mx = -INFINITY;
#pragma unroll
            for (int u = 0; u < 4; u++)
#pragma unroll
                for (int v2 = 0; v2 < 4; v2++)
                    mx = fmaxf(mx, a8[c * 64 + (qi * 4 + u) * 8 + qj * 4 + v2]);
            dst[tid] = cavg[tid] + mx;
        }
        __syncthreads();
    }

    // ---- l2norm of centers ----
    if (tid < 4) {
        float s = 0.f;
#pragma unroll
        for (int c = 0; c < HDIM; c++) { float v = ctrs[tid * 32 + c]; s += v * v; }
        cnorm[tid] = fmaxf(sqrtf(s), 1e-12f);
    }
    __syncthreads();
    if (tid < 128) cns[tid] = ctrs[tid] / cnorm[tid >> 5];
    __syncthreads();

    const float alpha = alphaP[0], beta = betaP[0];

    // ---- sim + argmax per token ----
#pragma unroll
    for (int rep = 0; rep < 4; rep++) {
        int n = rep * 256 + tid;
        int wi = n >> 5, hj = n & 31;
        const float* px = xbase + wi * 64 + hj;
        float xt[32];
        float ss = 0.f;
#pragma unroll
        for (int c = 0; c < HDIM; c++) { float v = px[c * SPAT]; xt[c] = v; ss += v * v; }
        float inv = 1.f / fmaxf(sqrtf(ss), 1e-12f);
        float best = -1.f; int bm = 0;
#pragma unroll
        for (int m = 0; m < 4; m++) {
            float d = 0.f;
#pragma unroll
            for (int c = 0; c < HDIM; c++) d += cns[m * 32 + c] * xt[c];
            d *= inv;
            float sg = 1.f / (1.f + expf(-(beta + alpha * d)));
            if (sg > best) { best = sg; bm = m; }   // first-max wins (strict >)
        }
        simval[n] = best;
        mstar[n] = (unsigned char)bm;
    }
    __syncthreads();

    // ---- combine: acc[m][c] = sum_n masked sim * v ----
    {
        int warp = tid >> 5, lane = tid & 31;
#pragma unroll
        for (int cc = 0; cc < 4; cc++) {
            int c = warp * 4 + cc;
            const float* pv = vbase + (size_t)c * SPAT;
            float am0 = 0.f, am1 = 0.f, am2 = 0.f, am3 = 0.f;
            for (int q = 0; q < 32; q++) {
                int n = q * 32 + lane;
                float t2 = simval[n] * pv[q * 64 + lane];
                int m = mstar[n];
                am0 += (m == 0) ? t2 : 0.f;
                am1 += (m == 1) ? t2 : 0.f;
                am2 += (m == 2) ? t2 : 0.f;
                am3 += (m == 3) ? t2 : 0.f;
            }
            float am[4] = {am0, am1, am2, am3};
#pragma unroll
            for (int m = 0; m < 4; m++) {
                float s = am[m];
                for (int o = 16; o; o >>= 1) s += __shfl_down_sync(0xffffffffu, s, o);
                if (lane == 0) accs[m * 32 + c] = s;
            }
        }
        if (warp == 0) {
            float pc4[4] = {0.f, 0.f, 0.f, 0.f};
            for (int q = 0; q < 32; q++) pc4[mstar[q * 32 + lane]] += 1.f;
#pragma unroll
            for (int m = 0; m < 4; m++) {
                float s = pc4[m];
                for (int o = 16; o; o >>= 1) s += __shfl_down_sync(0xffffffffu, s, o);
                if (lane == 0) cnt[m] = s;
            }
        }
    }
    __syncthreads();
    if (tid < 128) outm[tid] = (accs[tid] + vcs[tid]) / (cnt[tid >> 5] + 1.f);
    __syncthreads();

    // ---- dispatch: token_out[n][c] = outm[m*][c] * sim[n]; write unfolded ----
    for (int idx = tid; idx < 32 * 1024; idx += 256) {
        int c = idx >> 10, n = idx & 1023;
        int wi = n >> 5, hj = n & 31;
        obase[(size_t)c * SPAT + wi * 64 + hj] = outm[mstar[n] * 32 + c] * simval[n];
    }
}

// ---------------- launcher ----------------
extern "C" void kernel_launch(void* const* d_in, const int* in_sizes, int n_in,
                              void* d_out, int out_size) {
    const float* x       = (const float*)d_in[0];
    const float* scaler  = (const float*)d_in[1];
    const float* w_fc1   = (const float*)d_in[2];
    const float* b_fc1   = (const float*)d_in[3];
    const float* w_fcv   = (const float*)d_in[4];
    const float* b_fcv   = (const float*)d_in[5];
    const float* w_fc2   = (const float*)d_in[6];
    const float* b_fc2   = (const float*)d_in[7];
    const float* alpha   = (const float*)d_in[8];
    const float* beta    = (const float*)d_in[9];
    const float* off_w1  = (const float*)d_in[10];
    const float* off_b1  = (const float*)d_in[11];
    const float* off_w2  = (const float*)d_in[12];
    const float* off_b2  = (const float*)d_in[13];
    float* out = (float*)d_out;

    int B = in_sizes[0] / (DIMC * SPAT);
    if (B > MAXB) B = MAXB;

    // device scratch pointers
    float *p_mean, *p_bb, *p_wcat, *p_xv, *p_x2;
    cudaGetSymbolAddress((void**)&p_mean, g_mean);
    cudaGetSymbolAddress((void**)&p_bb,   g_bb);
    cudaGetSymbolAddress((void**)&p_wcat, g_wcat);
    cudaGetSymbolAddress((void**)&p_xv,   g_xv);
    cudaGetSymbolAddress((void**)&p_x2,   g_x2);

    // 1. spatial means
    mean_kernel<<<B * DIMC, 256>>>(x, p_mean);
    // 2. weight concat + adjusted bias
    wcat_kernel<<<512, 256>>>(w_fc1, w_fcv);
    bias_kernel<<<(B * 512 + 255) / 256, 256>>>(w_fc1, b_fc1, w_fcv, b_fcv, scaler, B);
    // 3. fused fc1+fcv GEMM on raw x (gap correction folded into bias)
    {
        dim3 grid(SPAT / BN, 512 / BM, B);
        sgemm_kernel<<<grid, 256>>>(p_wcat, x, p_bb, p_xv, 512, DIMC, SPAT, 1);
    }
    // 4. clustering per fold window
    cluster_kernel<<<B * 32, 256>>>(off_w1, off_b1, off_w2, off_b2, alpha, beta);
    // 5. fc2 GEMM -> output
    {
        dim3 grid(SPAT / BN, DIMC / BM, B);
        sgemm_kernel<<<grid, 256>>>(w_fc2, p_x2, b_fc2, out, DIMC, DIMC, SPAT, 0);
    }
}